// round 1
// baseline (speedup 1.0000x reference)
#include <cuda_runtime.h>
#include <math.h>

// Shapes (fixed by the problem)
#define T_   4
#define B_   2048
#define D_   512
#define H_   8
#define TB_  8192          // T*B
#define DH_  4096          // D*H
#define BD_  1048576       // B*D
#define TBD_ 4194304       // T*B*D  (also size of "out" part of output)

static const size_t TBDH_ = (size_t)TB_ * DH_;  // 33,554,432

// ---------------- scratch (static device globals; no allocation) ------------
__device__ float g_xs[(size_t)TB_ * D_];        // shortcut spikes [TB, D]
__device__ float g_ypre[3ULL * TB_ * DH_];      // pre-BN branch GEMM outputs
__device__ float g_q[(size_t)TB_ * DH_];        // q spikes, layout [row, c=d*8+h]
__device__ float g_k[(size_t)TB_ * DH_];        // k spikes, layout [row, c=d*8+h]
__device__ float g_p[(size_t)TB_ * DH_];        // proj input, layout [row, m=h*512+d]
__device__ float g_opre[(size_t)TB_ * D_];      // pre-BN proj output
__device__ float g_mu[3 * DH_];
__device__ float g_rstd[3 * DH_];
__device__ float g_omu[D_];
__device__ float g_orstd[D_];
__device__ float g_part[3ULL * 8 * DH_ * 2];    // per-rowgroup partial (sum, sumsq)
__device__ float g_opart[8ULL * D_ * 2];

// ---------------- Kernel 1: shortcut LIF ------------------------------------
// v += (x - v)/2 ; s = H(v - 1) ; v *= (1 - s).  All ops exact-match to ref.
__global__ void k_lif_in(const float* __restrict__ x) {
    int i = blockIdx.x * blockDim.x + threadIdx.x;
    if (i >= BD_) return;
    float v = 0.f;
#pragma unroll
    for (int t = 0; t < T_; t++) {
        float xt = x[t * BD_ + i];
        float d  = xt - v;
        v = v + d * 0.5f;                 // == (xt - v)/2 exactly
        float s = (v - 1.0f) >= 0.0f ? 1.0f : 0.0f;
        g_xs[t * BD_ + i] = s;
        v = v * (1.0f - s);
    }
}

// ---------------- Kernel 2: fp32 SGEMM, C = A * B^T (+bias) ------------------
// A: [M,K] row-major. Bm: [N,K] row-major. C: [M,N] row-major.
// Block tile 128x128, k-tile 16, 256 threads, 8x8 per thread.
// M,N divisible by 128; K divisible by 16 (true for all our calls).
__global__ __launch_bounds__(256) void k_sgemm_nt(
    const float* __restrict__ A, const float* __restrict__ Bm,
    const float* __restrict__ bias, float* __restrict__ C,
    int M, int N, int K)
{
    __shared__ float As[16][132];
    __shared__ float Bs[16][132];
    const int tid = threadIdx.x;
    const int tm = tid >> 4;      // 0..15
    const int tn = tid & 15;      // 0..15
    const float* Ab = A  + (size_t)blockIdx.y * 128 * K;
    const float* Bb = Bm + (size_t)blockIdx.x * 128 * K;

    float acc[8][8];
#pragma unroll
    for (int i = 0; i < 8; i++)
#pragma unroll
        for (int j = 0; j < 8; j++) acc[i][j] = 0.f;

    for (int k0 = 0; k0 < K; k0 += 16) {
#pragma unroll
        for (int i = 0; i < 2; i++) {
            int f  = tid + i * 256;       // 0..511 over 128 rows x 4 float4
            int r  = f >> 2;
            int kq = (f & 3) << 2;
            float4 va = *reinterpret_cast<const float4*>(Ab + (size_t)r * K + k0 + kq);
            As[kq + 0][r] = va.x; As[kq + 1][r] = va.y;
            As[kq + 2][r] = va.z; As[kq + 3][r] = va.w;
            float4 vb = *reinterpret_cast<const float4*>(Bb + (size_t)r * K + k0 + kq);
            Bs[kq + 0][r] = vb.x; Bs[kq + 1][r] = vb.y;
            Bs[kq + 2][r] = vb.z; Bs[kq + 3][r] = vb.w;
        }
        __syncthreads();
#pragma unroll
        for (int kk = 0; kk < 16; kk++) {
            float a[8], b[8];
#pragma unroll
            for (int j = 0; j < 8; j++) a[j] = As[kk][tm * 8 + j];
#pragma unroll
            for (int j = 0; j < 8; j++) b[j] = Bs[kk][tn * 8 + j];
#pragma unroll
            for (int i = 0; i < 8; i++)
#pragma unroll
                for (int j = 0; j < 8; j++)
                    acc[i][j] = fmaf(a[i], b[j], acc[i][j]);
        }
        __syncthreads();
    }
#pragma unroll
    for (int i = 0; i < 8; i++) {
        int row = blockIdx.y * 128 + tm * 8 + i;
#pragma unroll
        for (int j = 0; j < 8; j++) {
            int col = blockIdx.x * 128 + tn * 8 + j;
            float v = acc[i][j];
            if (bias) v += bias[col];
            C[(size_t)row * N + col] = v;
        }
    }
}

// ---------------- Kernel 3a: per-column partial stats (Kahan) ----------------
// grid: (cols/128, 8 rowgroups). Each thread: one column, 1024 rows.
__global__ void k_colstats_part(const float* __restrict__ Y,
                                float* __restrict__ part, int cols) {
    int c  = blockIdx.x * 128 + threadIdx.x;
    int rg = blockIdx.y;
    const float* p = Y + (size_t)rg * 1024 * cols + c;
    float s = 0.f, cs = 0.f, q = 0.f, cq = 0.f;
    for (int r = 0; r < 1024; r++) {
        float v = p[(size_t)r * cols];
        float y1 = v - cs;  float t1 = s + y1;  cs = (t1 - s) - y1;  s = t1;
        float v2 = v * v;
        float y2 = v2 - cq; float t2 = q + y2;  cq = (t2 - q) - y2;  q = t2;
    }
    part[((size_t)rg * cols + c) * 2 + 0] = s;
    part[((size_t)rg * cols + c) * 2 + 1] = q;
}

// ---------------- Kernel 3b: finalize stats ----------------------------------
__global__ void k_colstats_fin(const float* __restrict__ part,
                               float* __restrict__ mu, float* __restrict__ rstd,
                               int cols) {
    int c = blockIdx.x * 256 + threadIdx.x;
    if (c >= cols) return;
    float s = 0.f, q = 0.f;
    for (int rg = 0; rg < 8; rg++) {
        s += part[((size_t)rg * cols + c) * 2 + 0];
        q += part[((size_t)rg * cols + c) * 2 + 1];
    }
    const float invn = 1.0f / 8192.0f;      // exact power of 2
    float m   = s * invn;
    float var = q * invn - m * m;
    mu[c]   = m;
    rstd[c] = 1.0f / sqrtf(var + 1e-5f);
}

// ---------------- Kernel 4: BN + LIF per branch ------------------------------
// thread = (b, c) with c = d*H + h.  vmode: 0 -> write [row, c]; 1 -> write v
// spikes in output layout [row, h*512 + d].
__global__ void k_bn_lif(const float* __restrict__ Y, const float* __restrict__ mu,
                         const float* __restrict__ rstd, const float* __restrict__ gg,
                         const float* __restrict__ bb, float* __restrict__ dst,
                         int vmode) {
    int i = blockIdx.x * 256 + threadIdx.x;
    if (i >= B_ * DH_) return;
    int b = i >> 12;          // / 4096
    int c = i & 4095;
    float m = mu[c], rs = rstd[c], gv = gg[c], bv = bb[c];
    int outc = vmode ? ((c & 7) * 512 + (c >> 3)) : c;
    float vm = 0.f;
#pragma unroll
    for (int t = 0; t < T_; t++) {
        int row = t * B_ + b;
        float xv = Y[(size_t)row * DH_ + c];
        float y = gv * (xv - m);          // match ref op order: g*(x-mu)*rstd + b
        y = y * rs;
        y = y + bv;
        float d = y - vm;
        vm = vm + d * 0.5f;
        float s = (vm - 1.0f) >= 0.0f ? 1.0f : 0.0f;
        dst[(size_t)row * DH_ + outc] = s;
        vm = vm * (1.0f - s);
    }
}

// ---------------- Kernel 5: kv = sum_h k*v ; LIF(0.5) ; P = q*kvs ------------
// thread = (b, d).  k,q layout [row, d*8+h]; v layout [row, h*512+d].
// kv values are small integers -> LIF here is bit-exact vs reference.
__global__ void k_kv_q(const float* __restrict__ Vout) {
    int i = blockIdx.x * 256 + threadIdx.x;
    if (i >= BD_) return;
    int b  = i >> 9;          // / 512
    int dd = i & 511;
    float vm = 0.f;
#pragma unroll
    for (int t = 0; t < T_; t++) {
        int row = t * B_ + b;
        size_t rb = (size_t)row * DH_;
        float kv = 0.f;
#pragma unroll
        for (int h = 0; h < H_; h++)
            kv += g_k[rb + dd * 8 + h] * Vout[rb + h * 512 + dd];
        float d = kv - vm;
        vm = vm + d * 0.5f;
        float s = (vm - 0.5f) >= 0.0f ? 1.0f : 0.0f;
        vm = vm * (1.0f - s);
#pragma unroll
        for (int h = 0; h < H_; h++)
            g_p[rb + h * 512 + dd] = g_q[rb + dd * 8 + h] * s;
    }
}

// ---------------- Kernel 6: final BN + residual ------------------------------
__global__ void k_bn_add(const float* __restrict__ x, const float* __restrict__ gp,
                         const float* __restrict__ bp, float* __restrict__ out) {
    int i = blockIdx.x * 256 + threadIdx.x;
    if (i >= TBD_) return;
    int c = i & 511;
    float v = g_opre[i];
    float y = gp[c] * (v - g_omu[c]);
    y = y * g_orstd[c];
    y = y + bp[c];
    out[i] = y + x[i];
}

// ---------------- launch -----------------------------------------------------
extern "C" void kernel_launch(void* const* d_in, const int* in_sizes, int n_in,
                              void* d_out, int out_size) {
    const float* x     = (const float*)d_in[0];
    const float* wq    = (const float*)d_in[1];
    const float* gq    = (const float*)d_in[2];
    const float* bq    = (const float*)d_in[3];
    const float* wk    = (const float*)d_in[4];
    const float* gk    = (const float*)d_in[5];
    const float* bk    = (const float*)d_in[6];
    const float* wv    = (const float*)d_in[7];
    const float* gv    = (const float*)d_in[8];
    const float* bv    = (const float*)d_in[9];
    const float* wproj = (const float*)d_in[10];
    const float* bproj = (const float*)d_in[11];
    const float* gp    = (const float*)d_in[12];
    const float* bp    = (const float*)d_in[13];

    float* out  = (float*)d_out;
    float* vout = out + TBD_;     // v spikes are second half of the output

    float *p_xs, *p_ypre, *p_q, *p_k, *p_p, *p_opre;
    float *p_mu, *p_rstd, *p_omu, *p_orstd, *p_part, *p_opart;
    cudaGetSymbolAddress((void**)&p_xs,    g_xs);
    cudaGetSymbolAddress((void**)&p_ypre,  g_ypre);
    cudaGetSymbolAddress((void**)&p_q,     g_q);
    cudaGetSymbolAddress((void**)&p_k,     g_k);
    cudaGetSymbolAddress((void**)&p_p,     g_p);
    cudaGetSymbolAddress((void**)&p_opre,  g_opre);
    cudaGetSymbolAddress((void**)&p_mu,    g_mu);
    cudaGetSymbolAddress((void**)&p_rstd,  g_rstd);
    cudaGetSymbolAddress((void**)&p_omu,   g_omu);
    cudaGetSymbolAddress((void**)&p_orstd, g_orstd);
    cudaGetSymbolAddress((void**)&p_part,  g_part);
    cudaGetSymbolAddress((void**)&p_opart, g_opart);

    // 1) shortcut LIF -> binary spikes
    k_lif_in<<<BD_ / 256, 256>>>(x);

    // 2) three branch GEMMs: [8192,512] x [512,4096]
    dim3 gb(DH_ / 128, TB_ / 128);   // (32, 64)
    k_sgemm_nt<<<gb, 256>>>(p_xs, wq, nullptr, p_ypre + 0 * TBDH_, TB_, DH_, D_);
    k_sgemm_nt<<<gb, 256>>>(p_xs, wk, nullptr, p_ypre + 1 * TBDH_, TB_, DH_, D_);
    k_sgemm_nt<<<gb, 256>>>(p_xs, wv, nullptr, p_ypre + 2 * TBDH_, TB_, DH_, D_);

    // 3) BN stats per branch
    for (int br = 0; br < 3; br++) {
        k_colstats_part<<<dim3(DH_ / 128, 8), 128>>>(p_ypre + (size_t)br * TBDH_,
                                                     p_part + (size_t)br * 8 * DH_ * 2, DH_);
        k_colstats_fin<<<DH_ / 256, 256>>>(p_part + (size_t)br * 8 * DH_ * 2,
                                           p_mu + br * DH_, p_rstd + br * DH_, DH_);
    }

    // 4) BN + LIF: q, k to scratch; v straight into the output buffer
    int nb4 = (B_ * DH_) / 256;
    k_bn_lif<<<nb4, 256>>>(p_ypre + 0 * TBDH_, p_mu + 0 * DH_, p_rstd + 0 * DH_, gq, bq, p_q, 0);
    k_bn_lif<<<nb4, 256>>>(p_ypre + 1 * TBDH_, p_mu + 1 * DH_, p_rstd + 1 * DH_, gk, bk, p_k, 0);
    k_bn_lif<<<nb4, 256>>>(p_ypre + 2 * TBDH_, p_mu + 2 * DH_, p_rstd + 2 * DH_, gv, bv, vout, 1);

    // 5) talking heads: kv, LIF(0.5), q*kv -> proj input
    k_kv_q<<<BD_ / 256, 256>>>(vout);

    // 6) proj GEMM: [8192,4096] x [4096,512] (+bias)
    k_sgemm_nt<<<dim3(D_ / 128, TB_ / 128), 256>>>(p_p, wproj, bproj, p_opre, TB_, D_, DH_);

    // 7) proj BN stats
    k_colstats_part<<<dim3(D_ / 128, 8), 128>>>(p_opre, p_opart, D_);
    k_colstats_fin<<<D_ / 256, 256>>>(p_opart, p_omu, p_orstd, D_);

    // 8) final BN + residual
    k_bn_add<<<TBD_ / 256, 256>>>(x, gp, bp, out);
}

// round 5
// speedup vs baseline: 2.4255x; 2.4255x over previous
#include <cuda_runtime.h>
#include <cuda_bf16.h>
#include <cstdint>
#include <math.h>

// Shapes (fixed by the problem)
#define T_   4
#define B_   2048
#define D_   512
#define H_   8
#define TB_  8192          // T*B
#define DH_  4096          // D*H
#define BD_  1048576       // B*D
#define TBD_ 4194304       // T*B*D

static const size_t TBDH_ = (size_t)TB_ * DH_;  // 33,554,432

// ---------------- scratch (static device globals; no allocation) ------------
__device__ __nv_bfloat16 g_xs[(size_t)TB_ * D_];     // shortcut spikes, bf16 (exact 0/1)
__device__ float g_ypre[3ULL * TB_ * DH_];           // pre-BN branch GEMM outputs
__device__ float g_q[(size_t)TB_ * DH_];             // q spikes [row, c=d*8+h]
__device__ float g_k[(size_t)TB_ * DH_];             // k spikes [row, c=d*8+h]
__device__ __nv_bfloat16 g_p[(size_t)TB_ * DH_];     // proj input spikes [row, h*512+d]
__device__ float g_opre[(size_t)TB_ * D_];           // pre-BN proj output
__device__ float g_mu[3 * DH_];
__device__ float g_rstd[3 * DH_];
__device__ float g_omu[D_];
__device__ float g_orstd[D_];
__device__ float g_part[3ULL * 8 * DH_ * 2];
__device__ float g_opart[8ULL * D_ * 2];
__device__ __nv_bfloat16 g_wc[3ULL * DH_ * 1536];    // branch weights split3: [br][n][hi|mid|lo]
__device__ __nv_bfloat16 g_wp[(size_t)D_ * 12288];   // proj weights split3

// ======================= PTX helpers =========================================
__device__ __forceinline__ uint32_t smem_u32(const void* p) {
    uint32_t a;
    asm("{ .reg .u64 t; cvta.to.shared.u64 t, %1; cvt.u32.u64 %0, t; }" : "=r"(a) : "l"(p));
    return a;
}
__device__ __forceinline__ void cp16(uint32_t smem, const void* g) {
    asm volatile("cp.async.cg.shared.global [%0], [%1], 16;" :: "r"(smem), "l"(g));
}
#define CP_COMMIT() asm volatile("cp.async.commit_group;" ::: "memory")
#define CP_WAIT0()  asm volatile("cp.async.wait_group 0;" ::: "memory")

__device__ __forceinline__ void ldm_x4(uint32_t* r, uint32_t addr) {
    asm volatile("ldmatrix.sync.aligned.m8n8.x4.shared.b16 {%0,%1,%2,%3}, [%4];"
                 : "=r"(r[0]), "=r"(r[1]), "=r"(r[2]), "=r"(r[3]) : "r"(addr));
}
// B fragment: NON-trans load from [n][k] row-major storage gives exactly the
// required (k-consecutive, n = lane/4) fragment for mma row.col.
__device__ __forceinline__ void ldm_x2(uint32_t* r, uint32_t addr) {
    asm volatile("ldmatrix.sync.aligned.m8n8.x2.shared.b16 {%0,%1}, [%2];"
                 : "=r"(r[0]), "=r"(r[1]) : "r"(addr));
}
__device__ __forceinline__ void mma16816(float* d, const uint32_t* a, const uint32_t* b) {
    asm volatile(
        "mma.sync.aligned.m16n8k16.row.col.f32.bf16.bf16.f32 "
        "{%0,%1,%2,%3}, {%4,%5,%6,%7}, {%8,%9}, {%0,%1,%2,%3};"
        : "+f"(d[0]), "+f"(d[1]), "+f"(d[2]), "+f"(d[3])
        : "r"(a[0]), "r"(a[1]), "r"(a[2]), "r"(a[3]), "r"(b[0]), "r"(b[1]));
}

// ======================= mma.sync bf16 GEMM ==================================
// C[M,N] = A[M,Ka] (K-cycled to Keff) x Bw[N,Keff]^T, fp32 out (+optional bias).
// CTA tile 128x128, K-stage 64 (128B swizzled rows), 8 warps (2x4, 64x32 each),
// double-buffered cp.async.
#define STAGE_BYTES 16384   // 128 rows * 128B (same for A and B tiles)
#define GEMM_SMEM   (4 * STAGE_BYTES)   // 65536

__global__ __launch_bounds__(256)
void k_mma_gemm(const __nv_bfloat16* __restrict__ A,
                const __nv_bfloat16* __restrict__ Bw,
                const float* __restrict__ bias,
                float* __restrict__ C,
                int M, int N, int Ka, int Keff)
{
    extern __shared__ __align__(128) char smem[];
    const uint32_t sA = smem_u32(smem);
    const uint32_t sB = sA + 2 * STAGE_BYTES;
    const int tid  = threadIdx.x;
    const int wid  = tid >> 5, lane = tid & 31;
    const int wm   = wid >> 2, wn = wid & 3;

    const __nv_bfloat16* Ab = A  + (size_t)blockIdx.y * 128 * Ka;
    const __nv_bfloat16* Bb = Bw + (size_t)blockIdx.x * 128 * (size_t)Keff;
    const int S = Keff >> 6;

    float acc[4][4][4];
#pragma unroll
    for (int mi = 0; mi < 4; mi++)
#pragma unroll
        for (int ni = 0; ni < 4; ni++)
#pragma unroll
            for (int j = 0; j < 4; j++) acc[mi][ni][j] = 0.f;

    auto load_stage = [&](int s, int buf) {
        int kb = s << 6;
        const __nv_bfloat16* Ag = Ab + (kb & (Ka - 1));   // Ka is a power of two
        const __nv_bfloat16* Bg = Bb + kb;
#pragma unroll
        for (int i = 0; i < 4; i++) {
            int q = tid + (i << 8);            // 0..1023 chunk id
            int r = q >> 3, c = q & 7;
            uint32_t off = (uint32_t)r * 128 + (uint32_t)((c ^ (r & 7)) << 4);
            cp16(sA + buf * STAGE_BYTES + off, Ag + (size_t)r * Ka + (c << 3));
            cp16(sB + buf * STAGE_BYTES + off, Bg + (size_t)r * Keff + (c << 3));
        }
    };

    load_stage(0, 0);
    CP_COMMIT();

    for (int s = 0; s < S; s++) {
        int cur = s & 1;
        CP_WAIT0();
        __syncthreads();
        if (s + 1 < S) { load_stage(s + 1, cur ^ 1); CP_COMMIT(); }

        uint32_t bA = sA + cur * STAGE_BYTES;
        uint32_t bB = sB + cur * STAGE_BYTES;
#pragma unroll
        for (int kk = 0; kk < 4; kk++) {
            uint32_t afr[4][4];
#pragma unroll
            for (int mi = 0; mi < 4; mi++) {
                int row = wm * 64 + mi * 16 + (lane & 15);
                int c   = (kk << 1) + (lane >> 4);
                ldm_x4(afr[mi], bA + (uint32_t)row * 128 + (uint32_t)((c ^ (row & 7)) << 4));
            }
            uint32_t bfr[4][2];
#pragma unroll
            for (int ni = 0; ni < 4; ni++) {
                int n = wn * 32 + ni * 8 + (lane & 7);
                int c = (kk << 1) + ((lane >> 3) & 1);
                ldm_x2(bfr[ni], bB + (uint32_t)n * 128 + (uint32_t)((c ^ (n & 7)) << 4));
            }
#pragma unroll
            for (int mi = 0; mi < 4; mi++)
#pragma unroll
                for (int ni = 0; ni < 4; ni++)
                    mma16816(acc[mi][ni], afr[mi], bfr[ni]);
        }
        __syncthreads();
    }

    // ---------------- epilogue -------------------------------------------
    int grow  = lane >> 2;
    int gcol  = (lane & 3) * 2;
#pragma unroll
    for (int mi = 0; mi < 4; mi++) {
        int r0 = blockIdx.y * 128 + wm * 64 + mi * 16 + grow;
#pragma unroll
        for (int ni = 0; ni < 4; ni++) {
            int cc = blockIdx.x * 128 + wn * 32 + ni * 8 + gcol;
            float b0 = 0.f, b1 = 0.f;
            if (bias) { b0 = bias[cc]; b1 = bias[cc + 1]; }
            float2 v0 = make_float2(acc[mi][ni][0] + b0, acc[mi][ni][1] + b1);
            float2 v1 = make_float2(acc[mi][ni][2] + b0, acc[mi][ni][3] + b1);
            *reinterpret_cast<float2*>(C + (size_t)r0 * N + cc)       = v0;
            *reinterpret_cast<float2*>(C + (size_t)(r0 + 8) * N + cc) = v1;
        }
    }
}

// ======================= weight split3 =======================================
__global__ void k_split(const float* __restrict__ w, __nv_bfloat16* __restrict__ dst,
                        int NK, int K) {
    int i = blockIdx.x * 256 + threadIdx.x;
    if (i >= NK) return;
    int n = i / K, kk = i - n * K;
    float v = w[i];
    __nv_bfloat16 h = __float2bfloat16(v);
    float r1 = v - __bfloat162float(h);
    __nv_bfloat16 m = __float2bfloat16(r1);
    float r2 = r1 - __bfloat162float(m);
    __nv_bfloat16 l = __float2bfloat16(r2);
    size_t base = (size_t)n * 3 * K + kk;
    dst[base] = h; dst[base + K] = m; dst[base + 2 * K] = l;
}

// ======================= elementwise stages ==================================
__global__ void k_lif_in(const float* __restrict__ x) {
    int i = blockIdx.x * blockDim.x + threadIdx.x;
    if (i >= BD_) return;
    float v = 0.f;
#pragma unroll
    for (int t = 0; t < T_; t++) {
        float xt = x[t * BD_ + i];
        float d = xt - v;
        v = v + d * 0.5f;
        float s = (v - 1.0f) >= 0.0f ? 1.0f : 0.0f;
        g_xs[(size_t)t * BD_ + i] = __float2bfloat16(s);
        v = v * (1.0f - s);
    }
}

__global__ void k_colstats_part(const float* __restrict__ Y,
                                float* __restrict__ part, int cols) {
    int c = blockIdx.x * 128 + threadIdx.x;
    int rg = blockIdx.y;
    const float* p = Y + (size_t)rg * 1024 * cols + c;
    float s = 0.f, cs = 0.f, q = 0.f, cq = 0.f;
    for (int r = 0; r < 1024; r++) {
        float v = p[(size_t)r * cols];
        float y1 = v - cs;  float t1 = s + y1;  cs = (t1 - s) - y1;  s = t1;
        float v2 = v * v;
        float y2 = v2 - cq; float t2 = q + y2;  cq = (t2 - q) - y2;  q = t2;
    }
    part[((size_t)rg * cols + c) * 2 + 0] = s;
    part[((size_t)rg * cols + c) * 2 + 1] = q;
}

__global__ void k_colstats_fin(const float* __restrict__ part,
                               float* __restrict__ mu, float* __restrict__ rstd,
                               int cols) {
    int c = blockIdx.x * 256 + threadIdx.x;
    if (c >= cols) return;
    float s = 0.f, q = 0.f;
    for (int rg = 0; rg < 8; rg++) {
        s += part[((size_t)rg * cols + c) * 2 + 0];
        q += part[((size_t)rg * cols + c) * 2 + 1];
    }
    const float invn = 1.0f / 8192.0f;
    float m = s * invn;
    float var = q * invn - m * m;
    mu[c] = m;
    rstd[c] = 1.0f / sqrtf(var + 1e-5f);
}

__global__ void k_bn_lif(const float* __restrict__ Y, const float* __restrict__ mu,
                         const float* __restrict__ rstd, const float* __restrict__ gg,
                         const float* __restrict__ bb, float* __restrict__ dst,
                         int vmode) {
    int i = blockIdx.x * 256 + threadIdx.x;
    if (i >= B_ * DH_) return;
    int b = i >> 12;
    int c = i & 4095;
    float m = mu[c], rs = rstd[c], gv = gg[c], bv = bb[c];
    int outc = vmode ? ((c & 7) * 512 + (c >> 3)) : c;
    float vm = 0.f;
#pragma unroll
    for (int t = 0; t < T_; t++) {
        int row = t * B_ + b;
        float xv = Y[(size_t)row * DH_ + c];
        float y = gv * (xv - m);
        y = y * rs;
        y = y + bv;
        float d = y - vm;
        vm = vm + d * 0.5f;
        float s = (vm - 1.0f) >= 0.0f ? 1.0f : 0.0f;
        dst[(size_t)row * DH_ + outc] = s;
        vm = vm * (1.0f - s);
    }
}

__global__ void k_kv_q(const float* __restrict__ Vout) {
    int i = blockIdx.x * 256 + threadIdx.x;
    if (i >= BD_) return;
    int b = i >> 9;
    int dd = i & 511;
    float vm = 0.f;
#pragma unroll
    for (int t = 0; t < T_; t++) {
        int row = t * B_ + b;
        size_t rb = (size_t)row * DH_;
        float kv = 0.f;
#pragma unroll
        for (int h = 0; h < H_; h++)
            kv += g_k[rb + dd * 8 + h] * Vout[rb + h * 512 + dd];
        float d = kv - vm;
        vm = vm + d * 0.5f;
        float s = (vm - 0.5f) >= 0.0f ? 1.0f : 0.0f;
        vm = vm * (1.0f - s);
#pragma unroll
        for (int h = 0; h < H_; h++)
            g_p[rb + h * 512 + dd] = __float2bfloat16(g_q[rb + dd * 8 + h] * s);
    }
}

__global__ void k_bn_add(const float* __restrict__ x, const float* __restrict__ gp,
                         const float* __restrict__ bp, float* __restrict__ out) {
    int i = blockIdx.x * 256 + threadIdx.x;
    if (i >= TBD_) return;
    int c = i & 511;
    float v = g_opre[i];
    float y = gp[c] * (v - g_omu[c]);
    y = y * g_orstd[c];
    y = y + bp[c];
    out[i] = y + x[i];
}

// ======================= launch ==============================================
extern "C" void kernel_launch(void* const* d_in, const int* in_sizes, int n_in,
                              void* d_out, int out_size) {
    const float* x     = (const float*)d_in[0];
    const float* wq    = (const float*)d_in[1];
    const float* gq    = (const float*)d_in[2];
    const float* bq    = (const float*)d_in[3];
    const float* wk    = (const float*)d_in[4];
    const float* gk    = (const float*)d_in[5];
    const float* bk    = (const float*)d_in[6];
    const float* wv    = (const float*)d_in[7];
    const float* gv    = (const float*)d_in[8];
    const float* bv    = (const float*)d_in[9];
    const float* wproj = (const float*)d_in[10];
    const float* bproj = (const float*)d_in[11];
    const float* gp    = (const float*)d_in[12];
    const float* bp    = (const float*)d_in[13];

    float* out  = (float*)d_out;
    float* vout = out + TBD_;

    __nv_bfloat16 *p_xs, *p_p, *p_wc, *p_wp;
    float *p_ypre, *p_q, *p_k, *p_opre;
    float *p_mu, *p_rstd, *p_omu, *p_orstd, *p_part, *p_opart;
    cudaGetSymbolAddress((void**)&p_xs,    g_xs);
    cudaGetSymbolAddress((void**)&p_ypre,  g_ypre);
    cudaGetSymbolAddress((void**)&p_q,     g_q);
    cudaGetSymbolAddress((void**)&p_k,     g_k);
    cudaGetSymbolAddress((void**)&p_p,     g_p);
    cudaGetSymbolAddress((void**)&p_opre,  g_opre);
    cudaGetSymbolAddress((void**)&p_mu,    g_mu);
    cudaGetSymbolAddress((void**)&p_rstd,  g_rstd);
    cudaGetSymbolAddress((void**)&p_omu,   g_omu);
    cudaGetSymbolAddress((void**)&p_orstd, g_orstd);
    cudaGetSymbolAddress((void**)&p_part,  g_part);
    cudaGetSymbolAddress((void**)&p_opart, g_opart);
    cudaGetSymbolAddress((void**)&p_wc,    g_wc);
    cudaGetSymbolAddress((void**)&p_wp,    g_wp);

    cudaFuncSetAttribute(k_mma_gemm, cudaFuncAttributeMaxDynamicSharedMemorySize,
                         GEMM_SMEM);

    // 0) split fp32 weights into 3 exact bf16 planes along K
    const int nkb = DH_ * D_;
    k_split<<<(nkb + 255) / 256, 256>>>(wq, p_wc + 0ULL * DH_ * 1536, nkb, D_);
    k_split<<<(nkb + 255) / 256, 256>>>(wk, p_wc + 1ULL * DH_ * 1536, nkb, D_);
    k_split<<<(nkb + 255) / 256, 256>>>(wv, p_wc + 2ULL * DH_ * 1536, nkb, D_);
    k_split<<<(nkb + 255) / 256, 256>>>(wproj, p_wp, nkb, DH_);

    // 1) shortcut LIF -> bf16 spikes
    k_lif_in<<<BD_ / 256, 256>>>(x);

    // 2) three branch GEMMs: [8192,512(x3)] x [512*3,4096]
    dim3 gb(DH_ / 128, TB_ / 128);   // (32, 64)
    k_mma_gemm<<<gb, 256, GEMM_SMEM>>>(p_xs, p_wc + 0ULL * DH_ * 1536, nullptr,
                                       p_ypre + 0 * TBDH_, TB_, DH_, D_, 3 * D_);
    k_mma_gemm<<<gb, 256, GEMM_SMEM>>>(p_xs, p_wc + 1ULL * DH_ * 1536, nullptr,
                                       p_ypre + 1 * TBDH_, TB_, DH_, D_, 3 * D_);
    k_mma_gemm<<<gb, 256, GEMM_SMEM>>>(p_xs, p_wc + 2ULL * DH_ * 1536, nullptr,
                                       p_ypre + 2 * TBDH_, TB_, DH_, D_, 3 * D_);

    // 3) BN stats per branch
    for (int br = 0; br < 3; br++) {
        k_colstats_part<<<dim3(DH_ / 128, 8), 128>>>(p_ypre + (size_t)br * TBDH_,
                                                     p_part + (size_t)br * 8 * DH_ * 2, DH_);
        k_colstats_fin<<<DH_ / 256, 256>>>(p_part + (size_t)br * 8 * DH_ * 2,
                                           p_mu + br * DH_, p_rstd + br * DH_, DH_);
    }

    // 4) BN + LIF: q, k to scratch; v straight into output
    int nb4 = (B_ * DH_) / 256;
    k_bn_lif<<<nb4, 256>>>(p_ypre + 0 * TBDH_, p_mu + 0 * DH_, p_rstd + 0 * DH_, gq, bq, p_q, 0);
    k_bn_lif<<<nb4, 256>>>(p_ypre + 1 * TBDH_, p_mu + 1 * DH_, p_rstd + 1 * DH_, gk, bk, p_k, 0);
    k_bn_lif<<<nb4, 256>>>(p_ypre + 2 * TBDH_, p_mu + 2 * DH_, p_rstd + 2 * DH_, gv, bv, vout, 1);

    // 5) talking heads: kv, LIF(0.5), q*kv -> bf16 proj input
    k_kv_q<<<BD_ / 256, 256>>>(vout);

    // 6) proj GEMM: [8192,4096(x3)] x [4096*3,512] (+bias)
    k_mma_gemm<<<dim3(D_ / 128, TB_ / 128), 256, GEMM_SMEM>>>(
        p_p, p_wp, bproj, p_opre, TB_, D_, DH_, 3 * DH_);

    // 7) proj BN stats
    k_colstats_part<<<dim3(D_ / 128, 8), 128>>>(p_opre, p_opart, D_);
    k_colstats_fin<<<D_ / 256, 256>>>(p_opart, p_omu, p_orstd, D_);

    // 8) final BN + residual
    k_bn_add<<<TBD_ / 256, 256>>>(x, gp, bp, out);
}

// round 6
// speedup vs baseline: 2.9054x; 1.1979x over previous
#include <cuda_runtime.h>
#include <cuda_bf16.h>
#include <cstdint>
#include <math.h>

// Shapes (fixed by the problem)
#define T_   4
#define B_   2048
#define D_   512
#define H_   8
#define TB_  8192          // T*B
#define DH_  4096          // D*H
#define BD_  1048576       // B*D
#define TBD_ 4194304       // T*B*D

static const size_t TBDH_ = (size_t)TB_ * DH_;  // 33,554,432

// ---------------- scratch (static device globals; no allocation) ------------
__device__ __nv_bfloat16 g_xs[(size_t)TB_ * D_];     // shortcut spikes, bf16 (exact 0/1)
__device__ float g_ypre[3ULL * TB_ * DH_];           // pre-BN branch GEMM outputs
__device__ __nv_bfloat16 g_q[(size_t)TB_ * DH_];     // q spikes [row, c=d*8+h] (exact 0/1)
__device__ __nv_bfloat16 g_k[(size_t)TB_ * DH_];     // k spikes [row, c=d*8+h]
__device__ __nv_bfloat16 g_p[(size_t)TB_ * DH_];     // proj input spikes [row, h*512+d]
__device__ float g_opre[(size_t)TB_ * D_];           // pre-BN proj output
__device__ float g_mu[3 * DH_];
__device__ float g_rstd[3 * DH_];
__device__ float g_omu[D_];
__device__ float g_orstd[D_];
__device__ float g_part[3ULL * 128 * DH_ * 2];       // per-rowgroup (128) col partials
__device__ float g_opart[128ULL * D_ * 2];
__device__ __nv_bfloat16 g_wc[3ULL * DH_ * 1536];    // branch weights split3
__device__ __nv_bfloat16 g_wp[(size_t)D_ * 12288];   // proj weights split3

// ======================= PTX helpers =========================================
__device__ __forceinline__ uint32_t smem_u32(const void* p) {
    uint32_t a;
    asm("{ .reg .u64 t; cvta.to.shared.u64 t, %1; cvt.u32.u64 %0, t; }" : "=r"(a) : "l"(p));
    return a;
}
__device__ __forceinline__ void cp16(uint32_t smem, const void* g) {
    asm volatile("cp.async.cg.shared.global [%0], [%1], 16;" :: "r"(smem), "l"(g));
}
#define CP_COMMIT() asm volatile("cp.async.commit_group;" ::: "memory")
#define CP_WAIT0()  asm volatile("cp.async.wait_group 0;" ::: "memory")
#define CP_WAIT1()  asm volatile("cp.async.wait_group 1;" ::: "memory")

__device__ __forceinline__ void ldm_x4(uint32_t* r, uint32_t addr) {
    asm volatile("ldmatrix.sync.aligned.m8n8.x4.shared.b16 {%0,%1,%2,%3}, [%4];"
                 : "=r"(r[0]), "=r"(r[1]), "=r"(r[2]), "=r"(r[3]) : "r"(addr));
}
__device__ __forceinline__ void mma16816(float* d, const uint32_t* a, const uint32_t* b) {
    asm volatile(
        "mma.sync.aligned.m16n8k16.row.col.f32.bf16.bf16.f32 "
        "{%0,%1,%2,%3}, {%4,%5,%6,%7}, {%8,%9}, {%0,%1,%2,%3};"
        : "+f"(d[0]), "+f"(d[1]), "+f"(d[2]), "+f"(d[3])
        : "r"(a[0]), "r"(a[1]), "r"(a[2]), "r"(a[3]), "r"(b[0]), "r"(b[1]));
}

// ======================= mma.sync bf16 GEMM + fused col stats ================
// C[M,N] = A[M,Ka] (K-cycled to Keff) x Bw[N,Keff]^T (+bias), fp32 out.
// Also emits per-(rowgroup=by*2+wm, col) partial sum/sumsq for BN stats.
// CTA tile 128x128, K-stage 64 (128B swizzled rows), 8 warps (2x4, 64x32 each),
// 3-stage cp.async pipeline. blockIdx.z strides B/C/part (multi-branch launch).
#define STAGE_BYTES 16384   // 128 rows * 128B
#define NSTAGE 3
#define GEMM_SMEM   (2 * NSTAGE * STAGE_BYTES)   // 98304

__global__ __launch_bounds__(256)
void k_mma_gemm(const __nv_bfloat16* __restrict__ A,
                const __nv_bfloat16* __restrict__ Bw,
                const float* __restrict__ bias,
                float* __restrict__ C,
                float* __restrict__ part,
                int N, int Ka, int Keff,
                size_t strideB, size_t strideC, size_t strideP)
{
    extern __shared__ __align__(128) char smem[];
    const uint32_t sA = smem_u32(smem);
    const uint32_t sB = sA + NSTAGE * STAGE_BYTES;
    const int tid  = threadIdx.x;
    const int wid  = tid >> 5, lane = tid & 31;
    const int wm   = wid >> 2, wn = wid & 3;

    Bw   += (size_t)blockIdx.z * strideB;
    C    += (size_t)blockIdx.z * strideC;
    part += (size_t)blockIdx.z * strideP;

    const __nv_bfloat16* Ab = A  + (size_t)blockIdx.y * 128 * Ka;
    const __nv_bfloat16* Bb = Bw + (size_t)blockIdx.x * 128 * (size_t)Keff;
    const int S = Keff >> 6;

    float acc[4][4][4];
#pragma unroll
    for (int mi = 0; mi < 4; mi++)
#pragma unroll
        for (int ni = 0; ni < 4; ni++)
#pragma unroll
            for (int j = 0; j < 4; j++) acc[mi][ni][j] = 0.f;

    auto load_stage = [&](int s, int buf) {
        int kb = s << 6;
        const __nv_bfloat16* Ag = Ab + (kb & (Ka - 1));   // Ka is a power of two
        const __nv_bfloat16* Bg = Bb + kb;
#pragma unroll
        for (int i = 0; i < 4; i++) {
            int q = tid + (i << 8);            // 0..1023 chunk id
            int r = q >> 3, c = q & 7;
            uint32_t off = (uint32_t)r * 128 + (uint32_t)((c ^ (r & 7)) << 4);
            cp16(sA + buf * STAGE_BYTES + off, Ag + (size_t)r * Ka + (c << 3));
            cp16(sB + buf * STAGE_BYTES + off, Bg + (size_t)r * Keff + (c << 3));
        }
    };

    load_stage(0, 0);
    CP_COMMIT();
    if (S > 1) { load_stage(1, 1); CP_COMMIT(); }

    for (int s = 0; s < S; s++) {
        int buf = s % NSTAGE;
        if (s + 1 < S) CP_WAIT1(); else CP_WAIT0();
        __syncthreads();
        if (s + 2 < S) { load_stage(s + 2, (s + 2) % NSTAGE); CP_COMMIT(); }

        uint32_t bA = sA + buf * STAGE_BYTES;
        uint32_t bB = sB + buf * STAGE_BYTES;
#pragma unroll
        for (int kk = 0; kk < 4; kk++) {
            uint32_t afr[4][4];
#pragma unroll
            for (int mi = 0; mi < 4; mi++) {
                int row = wm * 64 + mi * 16 + (lane & 15);
                int c   = (kk << 1) + (lane >> 4);
                ldm_x4(afr[mi], bA + (uint32_t)row * 128 + (uint32_t)((c ^ (row & 7)) << 4));
            }
            // B: one x4 covers two ni blocks (16 n-rows x both k-chunks)
            uint32_t bfr[4][2];
#pragma unroll
            for (int np = 0; np < 2; np++) {
                int g  = lane >> 3;                       // 0..3
                int nr = wn * 32 + np * 16 + (g >> 1) * 8 + (lane & 7);
                int c  = (kk << 1) + (g & 1);
                uint32_t tmp[4];
                ldm_x4(tmp, bB + (uint32_t)nr * 128 + (uint32_t)((c ^ (nr & 7)) << 4));
                bfr[np * 2 + 0][0] = tmp[0]; bfr[np * 2 + 0][1] = tmp[1];
                bfr[np * 2 + 1][0] = tmp[2]; bfr[np * 2 + 1][1] = tmp[3];
            }
#pragma unroll
            for (int mi = 0; mi < 4; mi++)
#pragma unroll
                for (int ni = 0; ni < 4; ni++)
                    mma16816(acc[mi][ni], afr[mi], bfr[ni]);
        }
        __syncthreads();
    }

    // ---------------- epilogue: bias, store C, fused column stats ----------
    int grow = lane >> 2;
    int gcol = (lane & 3) * 2;
    if (bias) {
#pragma unroll
        for (int ni = 0; ni < 4; ni++) {
            int cc = blockIdx.x * 128 + wn * 32 + ni * 8 + gcol;
            float b0 = bias[cc], b1 = bias[cc + 1];
#pragma unroll
            for (int mi = 0; mi < 4; mi++) {
                acc[mi][ni][0] += b0; acc[mi][ni][1] += b1;
                acc[mi][ni][2] += b0; acc[mi][ni][3] += b1;
            }
        }
    }
#pragma unroll
    for (int mi = 0; mi < 4; mi++) {
        int r0 = blockIdx.y * 128 + wm * 64 + mi * 16 + grow;
#pragma unroll
        for (int ni = 0; ni < 4; ni++) {
            int cc = blockIdx.x * 128 + wn * 32 + ni * 8 + gcol;
            *reinterpret_cast<float2*>(C + (size_t)r0 * N + cc) =
                make_float2(acc[mi][ni][0], acc[mi][ni][1]);
            *reinterpret_cast<float2*>(C + (size_t)(r0 + 8) * N + cc) =
                make_float2(acc[mi][ni][2], acc[mi][ni][3]);
        }
    }
    // per-(rowgroup, col) partial sums: reduce 8 rows in-thread, 8 lanes via shfl
    int rowgrp = blockIdx.y * 2 + wm;
#pragma unroll
    for (int ni = 0; ni < 4; ni++) {
#pragma unroll
        for (int jj = 0; jj < 2; jj++) {
            float s = 0.f, q = 0.f;
#pragma unroll
            for (int mi = 0; mi < 4; mi++) {
                float v0 = acc[mi][ni][jj], v1 = acc[mi][ni][jj + 2];
                s += v0 + v1;
                q += v0 * v0 + v1 * v1;
            }
#pragma unroll
            for (int o = 4; o < 32; o <<= 1) {
                s += __shfl_xor_sync(0xffffffffu, s, o);
                q += __shfl_xor_sync(0xffffffffu, q, o);
            }
            if (grow == 0) {
                int cc = blockIdx.x * 128 + wn * 32 + ni * 8 + gcol + jj;
                size_t idx = ((size_t)rowgrp * N + cc) * 2;
                part[idx]     = s;
                part[idx + 1] = q;
            }
        }
    }
}

// ======================= stats finalize ======================================
__global__ void k_colstats_fin(const float* __restrict__ part,
                               float* __restrict__ mu, float* __restrict__ rstd,
                               int cols) {
    int c = blockIdx.x * 256 + threadIdx.x;
    if (c >= cols) return;
    float s = 0.f, cs = 0.f, q = 0.f, cq = 0.f;
    for (int rg = 0; rg < 128; rg++) {
        float vs = part[((size_t)rg * cols + c) * 2 + 0];
        float vq = part[((size_t)rg * cols + c) * 2 + 1];
        float y1 = vs - cs; float t1 = s + y1; cs = (t1 - s) - y1; s = t1;
        float y2 = vq - cq; float t2 = q + y2; cq = (t2 - q) - y2; q = t2;
    }
    const float invn = 1.0f / 8192.0f;
    float m = s * invn;
    float var = q * invn - m * m;
    mu[c] = m;
    rstd[c] = 1.0f / sqrtf(var + 1e-5f);
}

// ======================= weight split3 =======================================
__global__ void k_split3(const float* __restrict__ w0, const float* __restrict__ w1,
                         const float* __restrict__ w2, __nv_bfloat16* __restrict__ dst,
                         int NK, int K, size_t dstride) {
    int i = blockIdx.x * 256 + threadIdx.x;
    if (i >= NK) return;
    const float* w = (blockIdx.y == 0) ? w0 : (blockIdx.y == 1) ? w1 : w2;
    __nv_bfloat16* d = dst + (size_t)blockIdx.y * dstride;
    int n = i / K, kk = i - n * K;
    float v = w[i];
    __nv_bfloat16 h = __float2bfloat16(v);
    float r1 = v - __bfloat162float(h);
    __nv_bfloat16 m = __float2bfloat16(r1);
    float r2 = r1 - __bfloat162float(m);
    __nv_bfloat16 l = __float2bfloat16(r2);
    size_t base = (size_t)n * 3 * K + kk;
    d[base] = h; d[base + K] = m; d[base + 2 * K] = l;
}

__global__ void k_split(const float* __restrict__ w, __nv_bfloat16* __restrict__ dst,
                        int NK, int K) {
    int i = blockIdx.x * 256 + threadIdx.x;
    if (i >= NK) return;
    int n = i / K, kk = i - n * K;
    float v = w[i];
    __nv_bfloat16 h = __float2bfloat16(v);
    float r1 = v - __bfloat162float(h);
    __nv_bfloat16 m = __float2bfloat16(r1);
    float r2 = r1 - __bfloat162float(m);
    __nv_bfloat16 l = __float2bfloat16(r2);
    size_t base = (size_t)n * 3 * K + kk;
    dst[base] = h; dst[base + K] = m; dst[base + 2 * K] = l;
}

// ======================= elementwise stages ==================================
__global__ void k_lif_in(const float* __restrict__ x) {
    int i = blockIdx.x * blockDim.x + threadIdx.x;
    if (i >= BD_) return;
    float v = 0.f;
#pragma unroll
    for (int t = 0; t < T_; t++) {
        float xt = x[t * BD_ + i];
        float d = xt - v;
        v = v + d * 0.5f;
        float s = (v - 1.0f) >= 0.0f ? 1.0f : 0.0f;
        g_xs[(size_t)t * BD_ + i] = __float2bfloat16(s);
        v = v * (1.0f - s);
    }
}

// BN + LIF -> bf16 spikes (q, k)
__global__ void k_bn_lif_qk(const float* __restrict__ Y, const float* __restrict__ mu,
                            const float* __restrict__ rstd, const float* __restrict__ gg,
                            const float* __restrict__ bb, __nv_bfloat16* __restrict__ dst) {
    int i = blockIdx.x * 256 + threadIdx.x;
    if (i >= B_ * DH_) return;
    int b = i >> 12;
    int c = i & 4095;
    float m = mu[c], rs = rstd[c], gv = gg[c], bv = bb[c];
    float vm = 0.f;
#pragma unroll
    for (int t = 0; t < T_; t++) {
        int row = t * B_ + b;
        float xv = Y[(size_t)row * DH_ + c];
        float y = gv * (xv - m);
        y = y * rs;
        y = y + bv;
        float d = y - vm;
        vm = vm + d * 0.5f;
        float s = (vm - 1.0f) >= 0.0f ? 1.0f : 0.0f;
        dst[(size_t)row * DH_ + c] = __float2bfloat16(s);
        vm = vm * (1.0f - s);
    }
}

// BN + LIF -> fp32 v spikes straight into output, layout [row, h*512 + d]
__global__ void k_bn_lif_v(const float* __restrict__ Y, const float* __restrict__ mu,
                           const float* __restrict__ rstd, const float* __restrict__ gg,
                           const float* __restrict__ bb, float* __restrict__ dst) {
    int i = blockIdx.x * 256 + threadIdx.x;
    if (i >= B_ * DH_) return;
    int b = i >> 12;
    int c = i & 4095;
    float m = mu[c], rs = rstd[c], gv = gg[c], bv = bb[c];
    int outc = (c & 7) * 512 + (c >> 3);
    float vm = 0.f;
#pragma unroll
    for (int t = 0; t < T_; t++) {
        int row = t * B_ + b;
        float xv = Y[(size_t)row * DH_ + c];
        float y = gv * (xv - m);
        y = y * rs;
        y = y + bv;
        float d = y - vm;
        vm = vm + d * 0.5f;
        float s = (vm - 1.0f) >= 0.0f ? 1.0f : 0.0f;
        dst[(size_t)row * DH_ + outc] = s;
        vm = vm * (1.0f - s);
    }
}

__global__ void k_kv_q(const float* __restrict__ Vout) {
    int i = blockIdx.x * 256 + threadIdx.x;
    if (i >= BD_) return;
    int b = i >> 9;
    int dd = i & 511;
    float vm = 0.f;
#pragma unroll
    for (int t = 0; t < T_; t++) {
        int row = t * B_ + b;
        size_t rb = (size_t)row * DH_;
        float kv = 0.f;
#pragma unroll
        for (int h = 0; h < H_; h++)
            kv += __bfloat162float(g_k[rb + dd * 8 + h]) * Vout[rb + h * 512 + dd];
        float d = kv - vm;
        vm = vm + d * 0.5f;
        float s = (vm - 0.5f) >= 0.0f ? 1.0f : 0.0f;
        vm = vm * (1.0f - s);
#pragma unroll
        for (int h = 0; h < H_; h++) {
            float qv = __bfloat162float(g_q[rb + dd * 8 + h]);
            g_p[rb + h * 512 + dd] = __float2bfloat16(qv * s);
        }
    }
}

__global__ void k_bn_add(const float* __restrict__ x, const float* __restrict__ gp,
                         const float* __restrict__ bp, float* __restrict__ out) {
    int i = blockIdx.x * 256 + threadIdx.x;
    if (i >= TBD_) return;
    int c = i & 511;
    float v = g_opre[i];
    float y = gp[c] * (v - g_omu[c]);
    y = y * g_orstd[c];
    y = y + bp[c];
    out[i] = y + x[i];
}

// ======================= launch ==============================================
extern "C" void kernel_launch(void* const* d_in, const int* in_sizes, int n_in,
                              void* d_out, int out_size) {
    const float* x     = (const float*)d_in[0];
    const float* wq    = (const float*)d_in[1];
    const float* gq    = (const float*)d_in[2];
    const float* bq    = (const float*)d_in[3];
    const float* wk    = (const float*)d_in[4];
    const float* gk    = (const float*)d_in[5];
    const float* bk    = (const float*)d_in[6];
    const float* wv    = (const float*)d_in[7];
    const float* gv    = (const float*)d_in[8];
    const float* bv    = (const float*)d_in[9];
    const float* wproj = (const float*)d_in[10];
    const float* bproj = (const float*)d_in[11];
    const float* gp    = (const float*)d_in[12];
    const float* bp    = (const float*)d_in[13];

    float* out  = (float*)d_out;
    float* vout = out + TBD_;

    __nv_bfloat16 *p_xs, *p_q, *p_k, *p_p, *p_wc, *p_wp;
    float *p_ypre, *p_opre;
    float *p_mu, *p_rstd, *p_omu, *p_orstd, *p_part, *p_opart;
    cudaGetSymbolAddress((void**)&p_xs,    g_xs);
    cudaGetSymbolAddress((void**)&p_ypre,  g_ypre);
    cudaGetSymbolAddress((void**)&p_q,     g_q);
    cudaGetSymbolAddress((void**)&p_k,     g_k);
    cudaGetSymbolAddress((void**)&p_p,     g_p);
    cudaGetSymbolAddress((void**)&p_opre,  g_opre);
    cudaGetSymbolAddress((void**)&p_mu,    g_mu);
    cudaGetSymbolAddress((void**)&p_rstd,  g_rstd);
    cudaGetSymbolAddress((void**)&p_omu,   g_omu);
    cudaGetSymbolAddress((void**)&p_orstd, g_orstd);
    cudaGetSymbolAddress((void**)&p_part,  g_part);
    cudaGetSymbolAddress((void**)&p_opart, g_opart);
    cudaGetSymbolAddress((void**)&p_wc,    g_wc);
    cudaGetSymbolAddress((void**)&p_wp,    g_wp);

    cudaFuncSetAttribute(k_mma_gemm, cudaFuncAttributeMaxDynamicSharedMemorySize,
                         GEMM_SMEM);

    // 0) split fp32 weights into 3 exact bf16 planes along K
    const int nkb = DH_ * D_;
    k_split3<<<dim3((nkb + 255) / 256, 3), 256>>>(wq, wk, wv, p_wc, nkb, D_,
                                                  (size_t)DH_ * 1536);
    k_split<<<(nkb + 255) / 256, 256>>>(wproj, p_wp, nkb, DH_);

    // 1) shortcut LIF -> bf16 spikes
    k_lif_in<<<BD_ / 256, 256>>>(x);

    // 2) three branch GEMMs in one launch (z = branch), stats fused in epilogue
    const size_t PSTRIDE = 128ULL * DH_ * 2;
    k_mma_gemm<<<dim3(DH_ / 128, TB_ / 128, 3), 256, GEMM_SMEM>>>(
        p_xs, p_wc, nullptr, p_ypre, p_part,
        DH_, D_, 3 * D_, (size_t)DH_ * 1536, TBDH_, PSTRIDE);

    // 3) finalize BN stats per branch
    for (int br = 0; br < 3; br++)
        k_colstats_fin<<<DH_ / 256, 256>>>(p_part + (size_t)br * PSTRIDE,
                                           p_mu + br * DH_, p_rstd + br * DH_, DH_);

    // 4) BN + LIF: q, k -> bf16 scratch; v -> fp32 output (transposed cols)
    int nb4 = (B_ * DH_) / 256;
    k_bn_lif_qk<<<nb4, 256>>>(p_ypre + 0 * TBDH_, p_mu + 0 * DH_, p_rstd + 0 * DH_, gq, bq, p_q);
    k_bn_lif_qk<<<nb4, 256>>>(p_ypre + 1 * TBDH_, p_mu + 1 * DH_, p_rstd + 1 * DH_, gk, bk, p_k);
    k_bn_lif_v <<<nb4, 256>>>(p_ypre + 2 * TBDH_, p_mu + 2 * DH_, p_rstd + 2 * DH_, gv, bv, vout);

    // 5) talking heads: kv, LIF(0.5), q*kv -> bf16 proj input
    k_kv_q<<<BD_ / 256, 256>>>(vout);

    // 6) proj GEMM: [8192,4096(x3)] x [4096*3,512] (+bias), stats fused
    k_mma_gemm<<<dim3(D_ / 128, TB_ / 128, 1), 256, GEMM_SMEM>>>(
        p_p, p_wp, bproj, p_opre, p_opart,
        D_, DH_, 3 * DH_, 0, 0, 0);

    // 7) finalize proj stats
    k_colstats_fin<<<D_ / 256, 256>>>(p_opart, p_omu, p_orstd, D_);

    // 8) final BN + residual
    k_bn_add<<<TBD_ / 256, 256>>>(x, gp, bp, out);
}

// round 7
// speedup vs baseline: 4.0920x; 1.4084x over previous
#include <cuda_runtime.h>
#include <cuda_fp16.h>
#include <cstdint>
#include <math.h>

// Shapes (fixed by the problem)
#define T_   4
#define B_   2048
#define D_   512
#define H_   8
#define TB_  8192          // T*B
#define DH_  4096          // D*H
#define BD_  1048576       // B*D
#define TBD_ 4194304       // T*B*D

static const size_t TBDH_ = (size_t)TB_ * DH_;  // 33,554,432

#define SCALE_DN 0.000244140625f   // 2^-12
#define SCALE_UP 4096.0f           // 2^12

// ---------------- scratch (static device globals; no allocation) ------------
__device__ __half g_xs[(size_t)TB_ * 1024];          // shortcut spikes dual-half: [row][k]=s, [row][512+k]=s*2^-12
__device__ float g_ypre[3ULL * TB_ * DH_];           // pre-BN branch GEMM outputs
__device__ __half g_p[(size_t)TB_ * 8192];           // proj input dual-half: [row][m], [row][4096+m]
__device__ float g_opre[(size_t)TB_ * D_];           // pre-BN proj output
__device__ float g_mu[3 * DH_];
__device__ float g_rstd[3 * DH_];
__device__ float g_omu[D_];
__device__ float g_orstd[D_];
__device__ float g_part[3ULL * 128 * DH_ * 2];       // per-rowgroup (128) col partials
__device__ float g_opart[128ULL * D_ * 2];
__device__ __half g_wc[3ULL * DH_ * 1024];           // branch weights split2: [br][n][hi | mid*4096]
__device__ __half g_wp[(size_t)D_ * 8192];           // proj weights split2

// ======================= PTX helpers =========================================
__device__ __forceinline__ uint32_t smem_u32(const void* p) {
    uint32_t a;
    asm("{ .reg .u64 t; cvta.to.shared.u64 t, %1; cvt.u32.u64 %0, t; }" : "=r"(a) : "l"(p));
    return a;
}
__device__ __forceinline__ void cp16(uint32_t smem, const void* g) {
    asm volatile("cp.async.cg.shared.global [%0], [%1], 16;" :: "r"(smem), "l"(g));
}
#define CP_COMMIT() asm volatile("cp.async.commit_group;" ::: "memory")
#define CP_WAIT0()  asm volatile("cp.async.wait_group 0;" ::: "memory")
#define CP_WAIT1()  asm volatile("cp.async.wait_group 1;" ::: "memory")

__device__ __forceinline__ void ldm_x4(uint32_t* r, uint32_t addr) {
    asm volatile("ldmatrix.sync.aligned.m8n8.x4.shared.b16 {%0,%1,%2,%3}, [%4];"
                 : "=r"(r[0]), "=r"(r[1]), "=r"(r[2]), "=r"(r[3]) : "r"(addr));
}
__device__ __forceinline__ void mma16816(float* d, const uint32_t* a, const uint32_t* b) {
    asm volatile(
        "mma.sync.aligned.m16n8k16.row.col.f32.f16.f16.f32 "
        "{%0,%1,%2,%3}, {%4,%5,%6,%7}, {%8,%9}, {%0,%1,%2,%3};"
        : "+f"(d[0]), "+f"(d[1]), "+f"(d[2]), "+f"(d[3])
        : "r"(a[0]), "r"(a[1]), "r"(a[2]), "r"(a[3]), "r"(b[0]), "r"(b[1]));
}

// ======================= mma.sync fp16 GEMM + fused col stats ================
// C[M,N] = A[M,Keff] x Bw[N,Keff]^T (+bias), fp32 out; also emits per-
// (rowgroup=by*2+wm, col) partial sum/sumsq. CTA tile 128x128, K-stage 64
// (128B swizzled rows), 8 warps (2x4, 64x32 each), 3-stage cp.async pipeline.
#define STAGE_BYTES 16384   // 128 rows * 128B
#define NSTAGE 3
#define GEMM_SMEM   (2 * NSTAGE * STAGE_BYTES)   // 98304

__global__ __launch_bounds__(256)
void k_mma_gemm(const __half* __restrict__ A,
                const __half* __restrict__ Bw,
                const float* __restrict__ bias,
                float* __restrict__ C,
                float* __restrict__ part,
                int N, int Keff,
                size_t strideB, size_t strideC, size_t strideP)
{
    extern __shared__ __align__(128) char smem[];
    const uint32_t sA = smem_u32(smem);
    const uint32_t sB = sA + NSTAGE * STAGE_BYTES;
    const int tid  = threadIdx.x;
    const int wid  = tid >> 5, lane = tid & 31;
    const int wm   = wid >> 2, wn = wid & 3;

    Bw   += (size_t)blockIdx.z * strideB;
    C    += (size_t)blockIdx.z * strideC;
    part += (size_t)blockIdx.z * strideP;

    const __half* Ab = A  + (size_t)blockIdx.y * 128 * (size_t)Keff;
    const __half* Bb = Bw + (size_t)blockIdx.x * 128 * (size_t)Keff;
    const int S = Keff >> 6;

    float acc[4][4][4];
#pragma unroll
    for (int mi = 0; mi < 4; mi++)
#pragma unroll
        for (int ni = 0; ni < 4; ni++)
#pragma unroll
            for (int j = 0; j < 4; j++) acc[mi][ni][j] = 0.f;

    auto load_stage = [&](int s, int buf) {
        int kb = s << 6;
        const __half* Ag = Ab + kb;
        const __half* Bg = Bb + kb;
#pragma unroll
        for (int i = 0; i < 4; i++) {
            int q = tid + (i << 8);            // 0..1023 chunk id
            int r = q >> 3, c = q & 7;
            uint32_t off = (uint32_t)r * 128 + (uint32_t)((c ^ (r & 7)) << 4);
            cp16(sA + buf * STAGE_BYTES + off, Ag + (size_t)r * Keff + (c << 3));
            cp16(sB + buf * STAGE_BYTES + off, Bg + (size_t)r * Keff + (c << 3));
        }
    };

    load_stage(0, 0);
    CP_COMMIT();
    if (S > 1) { load_stage(1, 1); CP_COMMIT(); }

    for (int s = 0; s < S; s++) {
        int buf = s % NSTAGE;
        if (s + 1 < S) CP_WAIT1(); else CP_WAIT0();
        __syncthreads();
        if (s + 2 < S) { load_stage(s + 2, (s + 2) % NSTAGE); CP_COMMIT(); }

        uint32_t bA = sA + buf * STAGE_BYTES;
        uint32_t bB = sB + buf * STAGE_BYTES;
#pragma unroll
        for (int kk = 0; kk < 4; kk++) {
            uint32_t afr[4][4];
#pragma unroll
            for (int mi = 0; mi < 4; mi++) {
                int row = wm * 64 + mi * 16 + (lane & 15);
                int c   = (kk << 1) + (lane >> 4);
                ldm_x4(afr[mi], bA + (uint32_t)row * 128 + (uint32_t)((c ^ (row & 7)) << 4));
            }
            uint32_t bfr[4][2];
#pragma unroll
            for (int np = 0; np < 2; np++) {
                int g  = lane >> 3;                       // 0..3
                int nr = wn * 32 + np * 16 + (g >> 1) * 8 + (lane & 7);
                int c  = (kk << 1) + (g & 1);
                uint32_t tmp[4];
                ldm_x4(tmp, bB + (uint32_t)nr * 128 + (uint32_t)((c ^ (nr & 7)) << 4));
                bfr[np * 2 + 0][0] = tmp[0]; bfr[np * 2 + 0][1] = tmp[1];
                bfr[np * 2 + 1][0] = tmp[2]; bfr[np * 2 + 1][1] = tmp[3];
            }
#pragma unroll
            for (int mi = 0; mi < 4; mi++)
#pragma unroll
                for (int ni = 0; ni < 4; ni++)
                    mma16816(acc[mi][ni], afr[mi], bfr[ni]);
        }
        // no bottom sync needed: buffer reuse distance is 3 stages and the
        // top-of-loop barrier already orders compute(s-1) before loads(s+2).
    }

    // ---------------- epilogue: bias, store C, fused column stats ----------
    int grow = lane >> 2;
    int gcol = (lane & 3) * 2;
    if (bias) {
#pragma unroll
        for (int ni = 0; ni < 4; ni++) {
            int cc = blockIdx.x * 128 + wn * 32 + ni * 8 + gcol;
            float b0 = bias[cc], b1 = bias[cc + 1];
#pragma unroll
            for (int mi = 0; mi < 4; mi++) {
                acc[mi][ni][0] += b0; acc[mi][ni][1] += b1;
                acc[mi][ni][2] += b0; acc[mi][ni][3] += b1;
            }
        }
    }
#pragma unroll
    for (int mi = 0; mi < 4; mi++) {
        int r0 = blockIdx.y * 128 + wm * 64 + mi * 16 + grow;
#pragma unroll
        for (int ni = 0; ni < 4; ni++) {
            int cc = blockIdx.x * 128 + wn * 32 + ni * 8 + gcol;
            *reinterpret_cast<float2*>(C + (size_t)r0 * N + cc) =
                make_float2(acc[mi][ni][0], acc[mi][ni][1]);
            *reinterpret_cast<float2*>(C + (size_t)(r0 + 8) * N + cc) =
                make_float2(acc[mi][ni][2], acc[mi][ni][3]);
        }
    }
    int rowgrp = blockIdx.y * 2 + wm;
#pragma unroll
    for (int ni = 0; ni < 4; ni++) {
#pragma unroll
        for (int jj = 0; jj < 2; jj++) {
            float s = 0.f, q = 0.f;
#pragma unroll
            for (int mi = 0; mi < 4; mi++) {
                float v0 = acc[mi][ni][jj], v1 = acc[mi][ni][jj + 2];
                s += v0 + v1;
                q += v0 * v0 + v1 * v1;
            }
#pragma unroll
            for (int o = 4; o < 32; o <<= 1) {
                s += __shfl_xor_sync(0xffffffffu, s, o);
                q += __shfl_xor_sync(0xffffffffu, q, o);
            }
            if (grow == 0) {
                int cc = blockIdx.x * 128 + wn * 32 + ni * 8 + gcol + jj;
                size_t idx = ((size_t)rowgrp * N + cc) * 2;
                part[idx]     = s;
                part[idx + 1] = q;
            }
        }
    }
}

// ======================= stats finalize ======================================
__global__ void k_colstats_fin(const float* __restrict__ part,
                               float* __restrict__ mu, float* __restrict__ rstd,
                               int cols) {
    int c = blockIdx.x * 256 + threadIdx.x;
    if (c >= cols) return;
    float s = 0.f, cs = 0.f, q = 0.f, cq = 0.f;
    for (int rg = 0; rg < 128; rg++) {
        float vs = part[((size_t)rg * cols + c) * 2 + 0];
        float vq = part[((size_t)rg * cols + c) * 2 + 1];
        float y1 = vs - cs; float t1 = s + y1; cs = (t1 - s) - y1; s = t1;
        float y2 = vq - cq; float t2 = q + y2; cq = (t2 - q) - y2; q = t2;
    }
    const float invn = 1.0f / 8192.0f;
    float m = s * invn;
    float var = q * invn - m * m;
    mu[c] = m;
    rstd[c] = 1.0f / sqrtf(var + 1e-5f);
}

// ======================= weight split2 (fp16 hi + fp16 mid*4096) =============
__global__ void k_split2(const float* __restrict__ w0, const float* __restrict__ w1,
                         const float* __restrict__ w2, __half* __restrict__ dst,
                         int NK, int K, size_t dstride) {
    int i = blockIdx.x * 256 + threadIdx.x;
    if (i >= NK) return;
    const float* w = (blockIdx.y == 0) ? w0 : (blockIdx.y == 1) ? w1 : w2;
    __half* d = dst + (size_t)blockIdx.y * dstride;
    int n = i / K, kk = i - n * K;
    float v = w[i];
    __half h = __float2half_rn(v);
    float r1 = v - __half2float(h);
    __half m = __float2half_rn(r1 * SCALE_UP);   // *2^12: exact scaling, avoids fp16 denormals
    size_t base = (size_t)n * 2 * K + kk;
    d[base] = h; d[base + K] = m;
}

// ======================= elementwise stages ==================================
// shortcut LIF -> dual-half spikes: [row][d]=s, [row][512+d]=s*2^-12
__global__ void k_lif_in(const float* __restrict__ x) {
    int i = blockIdx.x * blockDim.x + threadIdx.x;
    if (i >= BD_) return;
    int b = i >> 9, d2 = i & 511;
    float v = 0.f;
#pragma unroll
    for (int t = 0; t < T_; t++) {
        float xt = x[t * BD_ + i];
        float d = xt - v;
        v = v + d * 0.5f;
        float s = (v - 1.0f) >= 0.0f ? 1.0f : 0.0f;
        size_t base = ((size_t)(t * B_ + b)) * 1024 + d2;
        g_xs[base]       = __float2half(s);
        g_xs[base + 512] = __float2half(s * SCALE_DN);
        v = v * (1.0f - s);
    }
}

// mega-fused: BN+LIF for q,k,v + kv-sum + kv-LIF(0.5) + p = q*kvs (dual-half)
__global__ __launch_bounds__(128)
void k_bnlif_kv(const float* __restrict__ Y,      // 3 branches, strided TBDH_
                const float* __restrict__ mu, const float* __restrict__ rstd,
                const float* __restrict__ gq, const float* __restrict__ bq,
                const float* __restrict__ gk, const float* __restrict__ bk,
                const float* __restrict__ gv, const float* __restrict__ bv,
                float* __restrict__ vout, __half* __restrict__ P)
{
    int i = blockIdx.x * 128 + threadIdx.x;
    if (i >= BD_) return;
    int b = i >> 9, dd = i & 511;
    int c0 = dd << 3;

    const float* Yb[3] = { Y, Y + TBDH_, Y + 2 * TBDH_ };
    const float* gs[3] = { gq, gk, gv };
    const float* bs[3] = { bq, bk, bv };
    float prm[3][4][8];
#pragma unroll
    for (int br = 0; br < 3; br++)
#pragma unroll
        for (int h = 0; h < 8; h++) {
            prm[br][0][h] = mu[br * DH_ + c0 + h];
            prm[br][1][h] = rstd[br * DH_ + c0 + h];
            prm[br][2][h] = gs[br][c0 + h];
            prm[br][3][h] = bs[br][c0 + h];
        }

    float uq[8], uk[8], uv[8], ukv = 0.f;
#pragma unroll
    for (int h = 0; h < 8; h++) { uq[h] = uk[h] = uv[h] = 0.f; }

#pragma unroll
    for (int t = 0; t < T_; t++) {
        int row = t * B_ + b;
        size_t rb = (size_t)row * DH_ + c0;
        float xq[8], xk[8], xv[8];
        *reinterpret_cast<float4*>(&xq[0]) = *reinterpret_cast<const float4*>(Yb[0] + rb);
        *reinterpret_cast<float4*>(&xq[4]) = *reinterpret_cast<const float4*>(Yb[0] + rb + 4);
        *reinterpret_cast<float4*>(&xk[0]) = *reinterpret_cast<const float4*>(Yb[1] + rb);
        *reinterpret_cast<float4*>(&xk[4]) = *reinterpret_cast<const float4*>(Yb[1] + rb + 4);
        *reinterpret_cast<float4*>(&xv[0]) = *reinterpret_cast<const float4*>(Yb[2] + rb);
        *reinterpret_cast<float4*>(&xv[4]) = *reinterpret_cast<const float4*>(Yb[2] + rb + 4);

        float sq[8];
        float kv = 0.f;
        size_t ob = (size_t)row * DH_ + dd;
#pragma unroll
        for (int h = 0; h < 8; h++) {
            // q branch (exact op order: g*(x-m); *rs; +b)
            float y = prm[0][2][h] * (xq[h] - prm[0][0][h]); y *= prm[0][1][h]; y += prm[0][3][h];
            float d = y - uq[h]; uq[h] = uq[h] + d * 0.5f;
            float s = (uq[h] - 1.0f) >= 0.f ? 1.f : 0.f; sq[h] = s; uq[h] *= (1.f - s);
            // k branch
            y = prm[1][2][h] * (xk[h] - prm[1][0][h]); y *= prm[1][1][h]; y += prm[1][3][h];
            d = y - uk[h]; uk[h] = uk[h] + d * 0.5f;
            float sk = (uk[h] - 1.0f) >= 0.f ? 1.f : 0.f; uk[h] *= (1.f - sk);
            // v branch
            y = prm[2][2][h] * (xv[h] - prm[2][0][h]); y *= prm[2][1][h]; y += prm[2][3][h];
            d = y - uv[h]; uv[h] = uv[h] + d * 0.5f;
            float sv = (uv[h] - 1.0f) >= 0.f ? 1.f : 0.f; uv[h] *= (1.f - sv);

            vout[ob + (h << 9)] = sv;          // output layout [row, h*512+d]
            kv += sk * sv;                      // exact small integers
        }
        float d2 = kv - ukv; ukv = ukv + d2 * 0.5f;
        float skv = (ukv - 0.5f) >= 0.f ? 1.f : 0.f; ukv *= (1.f - skv);

        size_t pb = (size_t)row * 8192 + dd;
#pragma unroll
        for (int h = 0; h < 8; h++) {
            float pv = sq[h] * skv;            // binary
            P[pb + (h << 9)]        = __float2half(pv);
            P[pb + 4096 + (h << 9)] = __float2half(pv * SCALE_DN);
        }
    }
}

__global__ void k_bn_add(const float* __restrict__ x, const float* __restrict__ gp,
                         const float* __restrict__ bp, float* __restrict__ out) {
    int i = blockIdx.x * 256 + threadIdx.x;
    if (i >= TBD_) return;
    int c = i & 511;
    float v = g_opre[i];
    float y = gp[c] * (v - g_omu[c]);
    y = y * g_orstd[c];
    y = y + bp[c];
    out[i] = y + x[i];
}

// ======================= launch ==============================================
extern "C" void kernel_launch(void* const* d_in, const int* in_sizes, int n_in,
                              void* d_out, int out_size) {
    const float* x     = (const float*)d_in[0];
    const float* wq    = (const float*)d_in[1];
    const float* gq    = (const float*)d_in[2];
    const float* bq    = (const float*)d_in[3];
    const float* wk    = (const float*)d_in[4];
    const float* gk    = (const float*)d_in[5];
    const float* bk    = (const float*)d_in[6];
    const float* wv    = (const float*)d_in[7];
    const float* gv    = (const float*)d_in[8];
    const float* bv    = (const float*)d_in[9];
    const float* wproj = (const float*)d_in[10];
    const float* bproj = (const float*)d_in[11];
    const float* gp    = (const float*)d_in[12];
    const float* bp    = (const float*)d_in[13];

    float* out  = (float*)d_out;
    float* vout = out + TBD_;

    __half *p_xs, *p_p, *p_wc, *p_wp;
    float *p_ypre, *p_opre;
    float *p_mu, *p_rstd, *p_omu, *p_orstd, *p_part, *p_opart;
    cudaGetSymbolAddress((void**)&p_xs,    g_xs);
    cudaGetSymbolAddress((void**)&p_ypre,  g_ypre);
    cudaGetSymbolAddress((void**)&p_p,     g_p);
    cudaGetSymbolAddress((void**)&p_opre,  g_opre);
    cudaGetSymbolAddress((void**)&p_mu,    g_mu);
    cudaGetSymbolAddress((void**)&p_rstd,  g_rstd);
    cudaGetSymbolAddress((void**)&p_omu,   g_omu);
    cudaGetSymbolAddress((void**)&p_orstd, g_orstd);
    cudaGetSymbolAddress((void**)&p_part,  g_part);
    cudaGetSymbolAddress((void**)&p_opart, g_opart);
    cudaGetSymbolAddress((void**)&p_wc,    g_wc);
    cudaGetSymbolAddress((void**)&p_wp,    g_wp);

    cudaFuncSetAttribute(k_mma_gemm, cudaFuncAttributeMaxDynamicSharedMemorySize,
                         GEMM_SMEM);

    // 0) split fp32 weights into 2 fp16 planes (hi, mid*4096)
    const int nkb = DH_ * D_;
    k_split2<<<dim3((nkb + 255) / 256, 3), 256>>>(wq, wk, wv, p_wc, nkb, D_,
                                                  (size_t)DH_ * 1024);
    k_split2<<<dim3((nkb + 255) / 256, 1), 256>>>(wproj, wproj, wproj, p_wp, nkb, DH_, 0);

    // 1) shortcut LIF -> dual-half spikes
    k_lif_in<<<BD_ / 256, 256>>>(x);

    // 2) three branch GEMMs in one launch (z = branch), Keff = 1024, stats fused
    const size_t PSTRIDE = 128ULL * DH_ * 2;
    k_mma_gemm<<<dim3(DH_ / 128, TB_ / 128, 3), 256, GEMM_SMEM>>>(
        p_xs, p_wc, nullptr, p_ypre, p_part,
        DH_, 1024, (size_t)DH_ * 1024, TBDH_, PSTRIDE);

    // 3) finalize BN stats per branch
    for (int br = 0; br < 3; br++)
        k_colstats_fin<<<DH_ / 256, 256>>>(p_part + (size_t)br * PSTRIDE,
                                           p_mu + br * DH_, p_rstd + br * DH_, DH_);

    // 4) mega-fused BN+LIF(q,k,v) + kv + LIF(0.5) + p
    k_bnlif_kv<<<BD_ / 128, 128>>>(p_ypre, p_mu, p_rstd, gq, bq, gk, bk, gv, bv,
                                   vout, p_p);

    // 5) proj GEMM: Keff = 8192 (+bias), stats fused
    k_mma_gemm<<<dim3(D_ / 128, TB_ / 128, 1), 256, GEMM_SMEM>>>(
        p_p, p_wp, bproj, p_opre, p_opart,
        D_, 8192, 0, 0, 0);

    // 6) finalize proj stats
    k_colstats_fin<<<D_ / 256, 256>>>(p_opart, p_omu, p_orstd, D_);

    // 7) final BN + residual
    k_bn_add<<<TBD_ / 256, 256>>>(x, gp, bp, out);
}